// round 2
// baseline (speedup 1.0000x reference)
#include <cuda_runtime.h>
#include <math.h>

#define JW 6
#define ALPHA_C 14.04f            // 2.34 * J
#define GSZ 1024                  // G1 == G2 == 2*H
#define NANG 720
#define NDET 768
#define KPTS (NANG * NDET)
#define TWO_PI 6.283185307179586f

__device__ float2 g_grid[GSZ * GSZ];   // padded/shifted image, then row-FFT'd in place
__device__ float2 g_specT[GSZ * GSZ];  // transposed spectrum: specT[j][i] = FFT2[i][j]/1024
__device__ float2 g_kdata[KPTS];       // gathered nonuniform k-space samples

// ---------------------------------------------------------------------------
// I0 (modified Bessel), A&S 9.8.1 / 9.8.2, fp32. Used for both apodization
// normalizer and KB weights -> I0(alpha) factors cancel exactly.
// ---------------------------------------------------------------------------
__device__ __forceinline__ float i0f_dev(float z) {
    if (z < 3.75f) {
        float t = z * (1.0f / 3.75f);
        float t2 = t * t;
        return 1.0f + t2 * (3.5156229f + t2 * (3.0899424f + t2 * (1.2067492f
                     + t2 * (0.2659732f + t2 * (0.0360768f + t2 * 0.0045813f)))));
    } else {
        float ti = 3.75f / z;
        float p = 0.39894228f + ti * (0.01328592f + ti * (0.00225319f
                + ti * (-0.00157565f + ti * (0.00916281f + ti * (-0.02057706f
                + ti * (0.02635537f + ti * (-0.01647633f + ti * 0.00392377f)))))));
        return p * __expf(z) * rsqrtf(z);
    }
}

__device__ __forceinline__ float apod_val(int n, float i0a) {
    float u = (float)(n - 256) * (1.0f / (float)GSZ);
    float t = 3.14159265358979f * (float)JW * u;
    float arg = ALPHA_C * ALPHA_C - t * t;
    float s = sqrtf(fabsf(arg) + 1e-20f);
    float sh;
    if (arg > 0.0f) {
        float e = __expf(s);
        sh = 0.5f * (e - 1.0f / e);
    } else {
        sh = __sinf(s);
    }
    float F = (sh / s) * ((float)JW / i0a);
    return 1.0f / F;
}

// ---------------------------------------------------------------------------
// Kernel 1: apodize + center-pad + 2D ifftshift (fused)
// ---------------------------------------------------------------------------
__global__ void build_grid_kernel(const float* __restrict__ img) {
    int j = blockIdx.x * blockDim.x + threadIdx.x;
    int i = blockIdx.y;
    int ri = ((i + 512) & (GSZ - 1)) - 256;
    int ci = ((j + 512) & (GSZ - 1)) - 256;
    float2 v = make_float2(0.0f, 0.0f);
    if (ri >= 0 && ri < 512 && ci >= 0 && ci < 512) {
        float i0a = i0f_dev(ALPHA_C);
        v.x = img[ri * 512 + ci] * apod_val(ri, i0a) * apod_val(ci, i0a);
    }
    g_grid[i * GSZ + j] = v;
}

// ---------------------------------------------------------------------------
// Kernel 2: forward FFT along rows, 2 rows per block (shared twiddles).
// ---------------------------------------------------------------------------
__global__ void fft_rows_kernel() {
    __shared__ float2 sA[GSZ];
    __shared__ float2 sB[GSZ];
    float2* baseA = g_grid + (size_t)(2 * blockIdx.x) * GSZ;
    float2* baseB = baseA + GSZ;
    for (int t = threadIdx.x; t < GSZ; t += 256) {
        int bt = __brev(t) >> 22;
        sA[bt] = baseA[t];
        sB[bt] = baseB[t];
    }
    __syncthreads();
    #pragma unroll
    for (int st = 0; st < 10; ++st) {
        int half = 1 << st;
        int len = half << 1;
        #pragma unroll
        for (int q = 0; q < 2; ++q) {
            int t = threadIdx.x + q * 256;
            int grp = t >> st;
            int pos = t & (half - 1);
            int ii = grp * len + pos;
            int kk = ii + half;
            float ang = -TWO_PI * (float)pos / (float)len;
            float sw, cw;
            __sincosf(ang, &sw, &cw);
            float2 b = sA[kk];
            float2 wb = make_float2(b.x * cw - b.y * sw, b.x * sw + b.y * cw);
            float2 a = sA[ii];
            sA[ii] = make_float2(a.x + wb.x, a.y + wb.y);
            sA[kk] = make_float2(a.x - wb.x, a.y - wb.y);
            b = sB[kk];
            wb = make_float2(b.x * cw - b.y * sw, b.x * sw + b.y * cw);
            a = sB[ii];
            sB[ii] = make_float2(a.x + wb.x, a.y + wb.y);
            sB[kk] = make_float2(a.x - wb.x, a.y - wb.y);
        }
        __syncthreads();
    }
    for (int t = threadIdx.x; t < GSZ; t += 256) {
        baseA[t] = sA[t];
        baseB[t] = sB[t];
    }
}

// ---------------------------------------------------------------------------
// Kernel 3: forward FFT along columns, 2 columns per block via float4 strided
// loads (16B per lane per sector-touch); writes transposed + normalized.
// ---------------------------------------------------------------------------
__global__ void fft_cols_kernel() {
    __shared__ float2 sA[GSZ];
    __shared__ float2 sB[GSZ];
    int c = blockIdx.x;                          // column pair index 0..511
    const float4* src = (const float4*)g_grid;   // float4 = 2 adjacent float2 cols
    for (int t = threadIdx.x; t < GSZ; t += 256) {
        float4 v = src[(size_t)t * (GSZ / 2) + c];
        int bt = __brev(t) >> 22;
        sA[bt] = make_float2(v.x, v.y);
        sB[bt] = make_float2(v.z, v.w);
    }
    __syncthreads();
    #pragma unroll
    for (int st = 0; st < 10; ++st) {
        int half = 1 << st;
        int len = half << 1;
        #pragma unroll
        for (int q = 0; q < 2; ++q) {
            int t = threadIdx.x + q * 256;
            int grp = t >> st;
            int pos = t & (half - 1);
            int ii = grp * len + pos;
            int kk = ii + half;
            float ang = -TWO_PI * (float)pos / (float)len;
            float sw, cw;
            __sincosf(ang, &sw, &cw);
            float2 b = sA[kk];
            float2 wb = make_float2(b.x * cw - b.y * sw, b.x * sw + b.y * cw);
            float2 a = sA[ii];
            sA[ii] = make_float2(a.x + wb.x, a.y + wb.y);
            sA[kk] = make_float2(a.x - wb.x, a.y - wb.y);
            b = sB[kk];
            wb = make_float2(b.x * cw - b.y * sw, b.x * sw + b.y * cw);
            a = sB[ii];
            sB[ii] = make_float2(a.x + wb.x, a.y + wb.y);
            sB[kk] = make_float2(a.x - wb.x, a.y - wb.y);
        }
        __syncthreads();
    }
    const float scale = 1.0f / 1024.0f;
    float2* outA = g_specT + (size_t)(2 * c) * GSZ;
    float2* outB = outA + GSZ;
    for (int t = threadIdx.x; t < GSZ; t += 256) {
        float2 va = sA[t];
        float2 vb = sB[t];
        outA[t] = make_float2(va.x * scale, va.y * scale);
        outB[t] = make_float2(vb.x * scale, vb.y * scale);
    }
}

// ---------------------------------------------------------------------------
// Kernel 4: KB gridding gather. Fast path: 4 aligned float4 loads per row
// (8 float2 slots covering the 6 taps at either alignment parity).
// ---------------------------------------------------------------------------
__global__ void gather_kernel(const float* __restrict__ ksp) {
    int p = blockIdx.x * blockDim.x + threadIdx.x;
    if (p >= KPTS) return;

    const float c = (float)GSZ / TWO_PI;
    float g1 = fmodf(ksp[p] * c, (float)GSZ);          if (g1 < 0.0f) g1 += (float)GSZ;
    float g2 = fmodf(ksp[KPTS + p] * c, (float)GSZ);   if (g2 < 0.0f) g2 += (float)GSZ;

    int b1 = (int)floorf(g1);
    int b2 = (int)floorf(g2);

    float inv_i0a = 1.0f / i0f_dev(ALPHA_C);
    float wx[JW], wy[JW];
    #pragma unroll
    for (int j = 0; j < JW; ++j) {
        float u = g1 - (float)(b1 - 2 + j);
        float xx = fmaxf(1.0f - u * u * (1.0f / 9.0f), 0.0f);
        wx[j] = i0f_dev(ALPHA_C * sqrtf(xx)) * inv_i0a;
        float v = g2 - (float)(b2 - 2 + j);
        float yy = fmaxf(1.0f - v * v * (1.0f / 9.0f), 0.0f);
        wy[j] = i0f_dev(ALPHA_C * sqrtf(yy)) * inv_i0a;
    }

    float accx = 0.0f, accy = 0.0f;

    if (b1 >= 2 && b1 <= 1018 && b2 >= 2 && b2 <= 1020) {
        // No wrap in either dim: taps x in [b1-2, b1+3], y rows [b2-2, b2+3].
        int ix0 = b1 - 2;
        int a0  = ix0 & ~1;        // float4-aligned base (float2 units)
        int off = ix0 & 1;
        // shifted weights over the 8 loaded slots (branchless selects)
        float w0 = off ? 0.0f  : wx[0];
        float w1 = off ? wx[0] : wx[1];
        float w2 = off ? wx[1] : wx[2];
        float w3 = off ? wx[2] : wx[3];
        float w4 = off ? wx[3] : wx[4];
        float w5 = off ? wx[4] : wx[5];
        float w6 = off ? wx[5] : 0.0f;
        const float4* base = (const float4*)(g_specT + ((size_t)(b2 - 2) * GSZ + a0));
        #pragma unroll
        for (int bb = 0; bb < JW; ++bb) {
            const float4* rp = base + (size_t)bb * (GSZ / 2);
            float4 v0 = __ldg(rp);
            float4 v1 = __ldg(rp + 1);
            float4 v2 = __ldg(rp + 2);
            float4 v3 = __ldg(rp + 3);
            float px = v0.x * w0;
            float py = v0.y * w0;
            px = fmaf(v0.z, w1, px);  py = fmaf(v0.w, w1, py);
            px = fmaf(v1.x, w2, px);  py = fmaf(v1.y, w2, py);
            px = fmaf(v1.z, w3, px);  py = fmaf(v1.w, w3, py);
            px = fmaf(v2.x, w4, px);  py = fmaf(v2.y, w4, py);
            px = fmaf(v2.z, w5, px);  py = fmaf(v2.w, w5, py);
            px = fmaf(v3.x, w6, px);  py = fmaf(v3.y, w6, py);
            accx = fmaf(px, wy[bb], accx);
            accy = fmaf(py, wy[bb], accy);
        }
    } else {
        // Slow path with wrapping (rare: near k-space center / edges)
        int ix[JW], iy[JW];
        #pragma unroll
        for (int j = 0; j < JW; ++j) {
            ix[j] = (b1 - 2 + j + GSZ) & (GSZ - 1);
            iy[j] = (b2 - 2 + j + GSZ) & (GSZ - 1);
        }
        #pragma unroll
        for (int bb = 0; bb < JW; ++bb) {
            const float2* __restrict__ rowp = g_specT + (size_t)iy[bb] * GSZ;
            float px = 0.0f, py = 0.0f;
            #pragma unroll
            for (int aa = 0; aa < JW; ++aa) {
                float2 v = __ldg(&rowp[ix[aa]]);
                px = fmaf(v.x, wx[aa], px);
                py = fmaf(v.y, wx[aa], py);
            }
            accx = fmaf(px, wy[bb], accx);
            accy = fmaf(py, wy[bb], accy);
        }
    }
    g_kdata[p] = make_float2(accx, accy);
}

// ---------------------------------------------------------------------------
// Kernel 5: per-angle 768-pt inverse FFT (3 x 256 mixed radix), shifts folded.
// ---------------------------------------------------------------------------
__global__ void ifft768_kernel(float* __restrict__ out) {
    __shared__ float2 sY[3][256];
    int a = blockIdx.x;
    const float2* rowin = g_kdata + (size_t)a * NDET;

    int r = threadIdx.x >> 7;
    int lt = threadIdx.x & 127;

    for (int m = lt; m < 256; m += 128) {
        int src = (3 * m + r + 384) % NDET;
        sY[r][__brev(m) >> 24] = rowin[src];
    }
    __syncthreads();

    #pragma unroll
    for (int st = 0; st < 8; ++st) {
        int half = 1 << st;
        int len = half << 1;
        int grp = lt >> st;
        int pos = lt & (half - 1);
        int ii = grp * len + pos;
        int kk = ii + half;
        float ang = TWO_PI * (float)pos / (float)len;
        float sw, cw;
        __sincosf(ang, &sw, &cw);
        float2 b = sY[r][kk];
        float2 wb = make_float2(b.x * cw - b.y * sw, b.x * sw + b.y * cw);
        float2 aa = sY[r][ii];
        sY[r][ii] = make_float2(aa.x + wb.x, aa.y + wb.y);
        sY[r][kk] = make_float2(aa.x - wb.x, aa.y - wb.y);
        __syncthreads();
    }

    const float inv = 1.0f / 768.0f;
    for (int k = threadIdx.x; k < NDET; k += 384) {
        int k0 = k & 255;
        float re = sY[0][k0].x;
        float a1 = TWO_PI * (float)k * (1.0f / 768.0f);
        float s1, c1;
        __sincosf(a1, &s1, &c1);
        re += sY[1][k0].x * c1 - sY[1][k0].y * s1;
        float s2, c2;
        __sincosf(a1 + a1, &s2, &c2);
        re += sY[2][k0].x * c2 - sY[2][k0].y * s2;
        out[(size_t)a * NDET + ((k + 384) % NDET)] = re * inv;
    }
}

// ---------------------------------------------------------------------------
extern "C" void kernel_launch(void* const* d_in, const int* in_sizes, int n_in,
                              void* d_out, int out_size) {
    const float* img = (const float*)d_in[0];
    const float* ksp = (const float*)d_in[1];
    float* out = (float*)d_out;

    build_grid_kernel<<<dim3(GSZ / 256, GSZ), 256>>>(img);
    fft_rows_kernel<<<GSZ / 2, 256>>>();
    fft_cols_kernel<<<GSZ / 2, 256>>>();
    gather_kernel<<<(KPTS + 255) / 256, 256>>>(ksp);
    ifft768_kernel<<<NANG, 384>>>(out);
}

// round 3
// speedup vs baseline: 1.0272x; 1.0272x over previous
#include <cuda_runtime.h>
#include <math.h>

#define JW 6
#define ALPHA_C 14.04f            // 2.34 * J
#define GSZ 1024                  // G1 == G2 == 2*H
#define NANG 720
#define NDET 768
#define KPTS (NANG * NDET)
#define TWO_PI 6.283185307179586f

__device__ float2 g_grid[GSZ * GSZ];   // padded/shifted image, then row-FFT'd in place
__device__ float2 g_specT[GSZ * GSZ];  // transposed spectrum: specT[j][i] = FFT2[i][j]/1024
__device__ float2 g_kdata[KPTS];       // gathered nonuniform k-space samples

// ---------------------------------------------------------------------------
// I0 (A&S 9.8.1/9.8.2) — used once per thread for the normalizer and in the
// apodization, so the I0(alpha) factors cancel exactly across the pipeline.
// ---------------------------------------------------------------------------
__device__ __forceinline__ float i0f_dev(float z) {
    if (z < 3.75f) {
        float t = z * (1.0f / 3.75f);
        float t2 = t * t;
        return 1.0f + t2 * (3.5156229f + t2 * (3.0899424f + t2 * (1.2067492f
                     + t2 * (0.2659732f + t2 * (0.0360768f + t2 * 0.0045813f)))));
    } else {
        float ti = 3.75f / z;
        float p = 0.39894228f + ti * (0.01328592f + ti * (0.00225319f
                + ti * (-0.00157565f + ti * (0.00916281f + ti * (-0.02057706f
                + ti * (0.02635537f + ti * (-0.01647633f + ti * 0.00392377f)))))));
        return p * __expf(z) * rsqrtf(z);
    }
}

// I0(alpha*sqrt(x)) for x in [0,1] as a pure-FMA power series in x:
// I0(a*sqrt(x)) = sum_k ( (a^2/4)^k / (k!)^2 ) x^k,  a^2/4 = 49.2804.
// Truncated at k=22 (next term ~1.3e-6 abs, ~1e-11 of peak). NO MUFU.
__device__ __forceinline__ float i0_alpha_sqrt(float x) {
    float s;
    s = 1.37184e-05f;
    s = fmaf(s, x, 1.34733e-04f);
    s = fmaf(s, x, 1.20570e-03f);
    s = fmaf(s, x, 9.78644e-03f);
    s = fmaf(s, x, 7.16895e-02f);
    s = fmaf(s, x, 4.71335e-01f);
    s = fmaf(s, x, 2.764070f);
    s = fmaf(s, x, 14.35870f);
    s = fmaf(s, x, 65.55800f);
    s = fmaf(s, x, 260.7380f);
    s = fmaf(s, x, 894.1610f);
    s = fmaf(s, x, 2612.787f);
    s = fmaf(s, x, 6415.273f);
    s = fmaf(s, x, 13017.90f);
    s = fmaf(s, x, 21396.99f);
    s = fmaf(s, x, 27788.08f);
    s = fmaf(s, x, 27629.97f);
    s = fmaf(s, x, 20184.07f);
    s = fmaf(s, x, 10239.40f);
    s = fmaf(s, x, 3324.453f);
    s = fmaf(s, x, 607.1395f);
    s = fmaf(s, x, 49.28040f);
    s = fmaf(s, x, 1.0f);
    return s;
}

__device__ __forceinline__ float apod_val(int n, float i0a) {
    float u = (float)(n - 256) * (1.0f / (float)GSZ);
    float t = 3.14159265358979f * (float)JW * u;
    float arg = ALPHA_C * ALPHA_C - t * t;
    float s = sqrtf(fabsf(arg) + 1e-20f);
    float sh;
    if (arg > 0.0f) {
        float e = __expf(s);
        sh = 0.5f * (e - 1.0f / e);
    } else {
        sh = __sinf(s);
    }
    float F = (sh / s) * ((float)JW / i0a);
    return 1.0f / F;
}

// ---------------------------------------------------------------------------
// Kernel 1: apodize + center-pad + 2D ifftshift (fused)
// ---------------------------------------------------------------------------
__global__ void build_grid_kernel(const float* __restrict__ img) {
    int j = blockIdx.x * blockDim.x + threadIdx.x;
    int i = blockIdx.y;
    int ri = ((i + 512) & (GSZ - 1)) - 256;
    int ci = ((j + 512) & (GSZ - 1)) - 256;
    float2 v = make_float2(0.0f, 0.0f);
    if (ri >= 0 && ri < 512 && ci >= 0 && ci < 512) {
        float i0a = i0f_dev(ALPHA_C);
        v.x = img[ri * 512 + ci] * apod_val(ri, i0a) * apod_val(ci, i0a);
    }
    g_grid[i * GSZ + j] = v;
}

// ---------------------------------------------------------------------------
// Shared-memory radix-2 FFT stages (input in bit-reversed order).
// ---------------------------------------------------------------------------
__device__ __forceinline__ void fft_stages_1024(float2* s, float sign) {
    #pragma unroll
    for (int st = 0; st < 10; ++st) {
        int half = 1 << st;
        int len = half << 1;
        #pragma unroll
        for (int q = 0; q < 2; ++q) {
            int t = threadIdx.x + q * 256;
            int grp = t >> st;
            int pos = t & (half - 1);
            int ii = grp * len + pos;
            int kk = ii + half;
            float ang = sign * TWO_PI * (float)pos / (float)len;
            float sw, cw;
            __sincosf(ang, &sw, &cw);
            float2 b = s[kk];
            float2 wb = make_float2(b.x * cw - b.y * sw, b.x * sw + b.y * cw);
            float2 a = s[ii];
            s[ii] = make_float2(a.x + wb.x, a.y + wb.y);
            s[kk] = make_float2(a.x - wb.x, a.y - wb.y);
        }
        __syncthreads();
    }
}

// Kernel 2: forward FFT along rows, in place. One block per row.
__global__ void fft_rows_kernel() {
    __shared__ float2 s[GSZ];
    float2* base = g_grid + (size_t)blockIdx.x * GSZ;
    for (int t = threadIdx.x; t < GSZ; t += 256) {
        s[__brev(t) >> 22] = base[t];
    }
    __syncthreads();
    fft_stages_1024(s, -1.0f);
    for (int t = threadIdx.x; t < GSZ; t += 256) {
        base[t] = s[t];
    }
}

// Kernel 3: forward FFT along columns; write transposed + normalized.
__global__ void fft_cols_kernel() {
    __shared__ float2 s[GSZ];
    int col = blockIdx.x;
    for (int t = threadIdx.x; t < GSZ; t += 256) {
        s[__brev(t) >> 22] = g_grid[(size_t)t * GSZ + col];
    }
    __syncthreads();
    fft_stages_1024(s, -1.0f);
    const float scale = 1.0f / 1024.0f;
    float2* outp = g_specT + (size_t)col * GSZ;
    for (int t = threadIdx.x; t < GSZ; t += 256) {
        float2 v = s[t];
        outp[t] = make_float2(v.x * scale, v.y * scale);
    }
}

// ---------------------------------------------------------------------------
// Kernel 4: KB gridding gather — MUFU-free weights (series in x),
// float4 vectorized fast path.
// ---------------------------------------------------------------------------
__global__ void gather_kernel(const float* __restrict__ ksp) {
    int p = blockIdx.x * blockDim.x + threadIdx.x;
    if (p >= KPTS) return;

    const float c = (float)GSZ / TWO_PI;
    float g1 = fmodf(ksp[p] * c, (float)GSZ);          if (g1 < 0.0f) g1 += (float)GSZ;
    float g2 = fmodf(ksp[KPTS + p] * c, (float)GSZ);   if (g2 < 0.0f) g2 += (float)GSZ;

    int b1 = (int)floorf(g1);
    int b2 = (int)floorf(g2);

    float inv_i0a = 1.0f / i0f_dev(ALPHA_C);   // cancels against apodization's i0a
    float wx[JW], wy[JW];
    #pragma unroll
    for (int j = 0; j < JW; ++j) {
        float u = g1 - (float)(b1 - 2 + j);
        float xx = fmaxf(fmaf(-u * u, (1.0f / 9.0f), 1.0f), 0.0f);
        wx[j] = i0_alpha_sqrt(xx) * inv_i0a;
        float v = g2 - (float)(b2 - 2 + j);
        float yy = fmaxf(fmaf(-v * v, (1.0f / 9.0f), 1.0f), 0.0f);
        wy[j] = i0_alpha_sqrt(yy) * inv_i0a;
    }

    float accx = 0.0f, accy = 0.0f;

    if (b1 >= 2 && b1 <= 1018 && b2 >= 2 && b2 <= 1020) {
        int ix0 = b1 - 2;
        int a0  = ix0 & ~1;        // float4-aligned base (float2 units)
        int off = ix0 & 1;
        float w0 = off ? 0.0f  : wx[0];
        float w1 = off ? wx[0] : wx[1];
        float w2 = off ? wx[1] : wx[2];
        float w3 = off ? wx[2] : wx[3];
        float w4 = off ? wx[3] : wx[4];
        float w5 = off ? wx[4] : wx[5];
        float w6 = off ? wx[5] : 0.0f;
        const float4* base = (const float4*)(g_specT + ((size_t)(b2 - 2) * GSZ + a0));
        #pragma unroll
        for (int bb = 0; bb < JW; ++bb) {
            const float4* rp = base + (size_t)bb * (GSZ / 2);
            float4 v0 = __ldg(rp);
            float4 v1 = __ldg(rp + 1);
            float4 v2 = __ldg(rp + 2);
            float4 v3 = __ldg(rp + 3);
            float px = v0.x * w0;
            float py = v0.y * w0;
            px = fmaf(v0.z, w1, px);  py = fmaf(v0.w, w1, py);
            px = fmaf(v1.x, w2, px);  py = fmaf(v1.y, w2, py);
            px = fmaf(v1.z, w3, px);  py = fmaf(v1.w, w3, py);
            px = fmaf(v2.x, w4, px);  py = fmaf(v2.y, w4, py);
            px = fmaf(v2.z, w5, px);  py = fmaf(v2.w, w5, py);
            px = fmaf(v3.x, w6, px);  py = fmaf(v3.y, w6, py);
            accx = fmaf(px, wy[bb], accx);
            accy = fmaf(py, wy[bb], accy);
        }
    } else {
        int ix[JW], iy[JW];
        #pragma unroll
        for (int j = 0; j < JW; ++j) {
            ix[j] = (b1 - 2 + j + GSZ) & (GSZ - 1);
            iy[j] = (b2 - 2 + j + GSZ) & (GSZ - 1);
        }
        #pragma unroll
        for (int bb = 0; bb < JW; ++bb) {
            const float2* __restrict__ rowp = g_specT + (size_t)iy[bb] * GSZ;
            float px = 0.0f, py = 0.0f;
            #pragma unroll
            for (int aa = 0; aa < JW; ++aa) {
                float2 v = __ldg(&rowp[ix[aa]]);
                px = fmaf(v.x, wx[aa], px);
                py = fmaf(v.y, wx[aa], py);
            }
            accx = fmaf(px, wy[bb], accx);
            accy = fmaf(py, wy[bb], accy);
        }
    }
    g_kdata[p] = make_float2(accx, accy);
}

// ---------------------------------------------------------------------------
// Kernel 5: per-angle 768-pt inverse FFT (3 x 256 mixed radix), shifts folded.
// ---------------------------------------------------------------------------
__global__ void ifft768_kernel(float* __restrict__ out) {
    __shared__ float2 sY[3][256];
    int a = blockIdx.x;
    const float2* rowin = g_kdata + (size_t)a * NDET;

    int r = threadIdx.x >> 7;
    int lt = threadIdx.x & 127;

    for (int m = lt; m < 256; m += 128) {
        int src = (3 * m + r + 384) % NDET;
        sY[r][__brev(m) >> 24] = rowin[src];
    }
    __syncthreads();

    #pragma unroll
    for (int st = 0; st < 8; ++st) {
        int half = 1 << st;
        int len = half << 1;
        int grp = lt >> st;
        int pos = lt & (half - 1);
        int ii = grp * len + pos;
        int kk = ii + half;
        float ang = TWO_PI * (float)pos / (float)len;
        float sw, cw;
        __sincosf(ang, &sw, &cw);
        float2 b = sY[r][kk];
        float2 wb = make_float2(b.x * cw - b.y * sw, b.x * sw + b.y * cw);
        float2 aa = sY[r][ii];
        sY[r][ii] = make_float2(aa.x + wb.x, aa.y + wb.y);
        sY[r][kk] = make_float2(aa.x - wb.x, aa.y - wb.y);
        __syncthreads();
    }

    const float inv = 1.0f / 768.0f;
    for (int k = threadIdx.x; k < NDET; k += 384) {
        int k0 = k & 255;
        float re = sY[0][k0].x;
        float a1 = TWO_PI * (float)k * (1.0f / 768.0f);
        float s1, c1;
        __sincosf(a1, &s1, &c1);
        re += sY[1][k0].x * c1 - sY[1][k0].y * s1;
        float s2, c2;
        __sincosf(a1 + a1, &s2, &c2);
        re += sY[2][k0].x * c2 - sY[2][k0].y * s2;
        out[(size_t)a * NDET + ((k + 384) % NDET)] = re * inv;
    }
}

// ---------------------------------------------------------------------------
extern "C" void kernel_launch(void* const* d_in, const int* in_sizes, int n_in,
                              void* d_out, int out_size) {
    const float* img = (const float*)d_in[0];
    const float* ksp = (const float*)d_in[1];
    float* out = (float*)d_out;

    build_grid_kernel<<<dim3(GSZ / 256, GSZ), 256>>>(img);
    fft_rows_kernel<<<GSZ, 256>>>();
    fft_cols_kernel<<<GSZ, 256>>>();
    gather_kernel<<<(KPTS + 255) / 256, 256>>>(ksp);
    ifft768_kernel<<<NANG, 384>>>(out);
}

// round 4
// speedup vs baseline: 1.3129x; 1.2782x over previous
#include <cuda_runtime.h>
#include <math.h>

#define JW 6
#define ALPHA_C 14.04f            // 2.34 * J
#define GSZ 1024                  // G1 == G2 == 2*H
#define NANG 720
#define NDET 768
#define KPTS (NANG * NDET)
#define NDHALF 385                // detectors actually gathered: d = 0..384
#define TWO_PI 6.283185307179586f

__device__ float2 g_grid[GSZ * GSZ];   // padded/shifted image, then row-FFT'd in place
__device__ float2 g_specT[GSZ * GSZ];  // transposed spectrum: specT[j][i] = FFT2[i][j]/1024
__device__ float2 g_kdata[KPTS];       // gathered nonuniform k-space samples

// ---------------------------------------------------------------------------
// I0 (A&S) — used for the normalizer and the apodization so I0(alpha) cancels.
// ---------------------------------------------------------------------------
__device__ __forceinline__ float i0f_dev(float z) {
    if (z < 3.75f) {
        float t = z * (1.0f / 3.75f);
        float t2 = t * t;
        return 1.0f + t2 * (3.5156229f + t2 * (3.0899424f + t2 * (1.2067492f
                     + t2 * (0.2659732f + t2 * (0.0360768f + t2 * 0.0045813f)))));
    } else {
        float ti = 3.75f / z;
        float p = 0.39894228f + ti * (0.01328592f + ti * (0.00225319f
                + ti * (-0.00157565f + ti * (0.00916281f + ti * (-0.02057706f
                + ti * (0.02635537f + ti * (-0.01647633f + ti * 0.00392377f)))))));
        return p * __expf(z) * rsqrtf(z);
    }
}

// I0(alpha*sqrt(x)) on [0,1]: power series in x, truncated at k=16
// (tail ~0.55 abs = 4e-6 of I0(alpha)). Pure FMA, no MUFU.
__device__ __forceinline__ float i0_alpha_sqrt(float x) {
    float s;
    s = 2.764070f;
    s = fmaf(s, x, 14.35870f);
    s = fmaf(s, x, 65.55800f);
    s = fmaf(s, x, 260.7380f);
    s = fmaf(s, x, 894.1610f);
    s = fmaf(s, x, 2612.787f);
    s = fmaf(s, x, 6415.273f);
    s = fmaf(s, x, 13017.90f);
    s = fmaf(s, x, 21396.99f);
    s = fmaf(s, x, 27788.08f);
    s = fmaf(s, x, 27629.97f);
    s = fmaf(s, x, 20184.07f);
    s = fmaf(s, x, 10239.40f);
    s = fmaf(s, x, 3324.453f);
    s = fmaf(s, x, 607.1395f);
    s = fmaf(s, x, 49.28040f);
    s = fmaf(s, x, 1.0f);
    return s;
}

__device__ __forceinline__ float apod_val(int n, float i0a) {
    float u = (float)(n - 256) * (1.0f / (float)GSZ);
    float t = 3.14159265358979f * (float)JW * u;
    float arg = ALPHA_C * ALPHA_C - t * t;
    float s = sqrtf(fabsf(arg) + 1e-20f);
    float sh;
    if (arg > 0.0f) {
        float e = __expf(s);
        sh = 0.5f * (e - 1.0f / e);
    } else {
        sh = __sinf(s);
    }
    float F = (sh / s) * ((float)JW / i0a);
    return 1.0f / F;
}

// ---------------------------------------------------------------------------
// Kernel 1: apodize + center-pad + 2D ifftshift (fused)
// ---------------------------------------------------------------------------
__global__ void build_grid_kernel(const float* __restrict__ img) {
    int j = blockIdx.x * blockDim.x + threadIdx.x;
    int i = blockIdx.y;
    int ri = ((i + 512) & (GSZ - 1)) - 256;
    int ci = ((j + 512) & (GSZ - 1)) - 256;
    float2 v = make_float2(0.0f, 0.0f);
    if (ri >= 0 && ri < 512 && ci >= 0 && ci < 512) {
        float i0a = i0f_dev(ALPHA_C);
        v.x = img[ri * 512 + ci] * apod_val(ri, i0a) * apod_val(ci, i0a);
    }
    g_grid[i * GSZ + j] = v;
}

// ---------------------------------------------------------------------------
// Shared-memory radix-2 FFT stages (input in bit-reversed order).
// ---------------------------------------------------------------------------
__device__ __forceinline__ void fft_stages_1024(float2* s, float sign) {
    #pragma unroll
    for (int st = 0; st < 10; ++st) {
        int half = 1 << st;
        int len = half << 1;
        #pragma unroll
        for (int q = 0; q < 2; ++q) {
            int t = threadIdx.x + q * 256;
            int grp = t >> st;
            int pos = t & (half - 1);
            int ii = grp * len + pos;
            int kk = ii + half;
            float ang = sign * TWO_PI * (float)pos / (float)len;
            float sw, cw;
            __sincosf(ang, &sw, &cw);
            float2 b = s[kk];
            float2 wb = make_float2(b.x * cw - b.y * sw, b.x * sw + b.y * cw);
            float2 a = s[ii];
            s[ii] = make_float2(a.x + wb.x, a.y + wb.y);
            s[kk] = make_float2(a.x - wb.x, a.y - wb.y);
        }
        __syncthreads();
    }
}

// Kernel 2: forward FFT along rows — ONLY the 512 nonzero rows
// (rows [0,256) and [768,1024); the rest are zero and stay zero).
__global__ void fft_rows_kernel() {
    __shared__ float2 s[GSZ];
    int b = blockIdx.x;
    int row = (b < 256) ? b : (b + 512);
    float2* base = g_grid + (size_t)row * GSZ;
    for (int t = threadIdx.x; t < GSZ; t += 256) {
        s[__brev(t) >> 22] = base[t];
    }
    __syncthreads();
    fft_stages_1024(s, -1.0f);
    for (int t = threadIdx.x; t < GSZ; t += 256) {
        base[t] = s[t];
    }
}

// Kernel 3: column FFT; rows [256,768) are known-zero -> no loads for them.
// Writes transposed + normalized spectrum.
__global__ void fft_cols_kernel() {
    __shared__ float2 s[GSZ];
    int col = blockIdx.x;
    {
        int t0 = threadIdx.x;            // in [0,256): nonzero row
        int t3 = threadIdx.x + 768;      // in [768,1024): nonzero row
        s[__brev(t0) >> 22] = g_grid[(size_t)t0 * GSZ + col];
        s[__brev(threadIdx.x + 256) >> 22] = make_float2(0.0f, 0.0f);
        s[__brev(threadIdx.x + 512) >> 22] = make_float2(0.0f, 0.0f);
        s[__brev(t3) >> 22] = g_grid[(size_t)t3 * GSZ + col];
    }
    __syncthreads();
    fft_stages_1024(s, -1.0f);
    const float scale = 1.0f / 1024.0f;
    float2* outp = g_specT + (size_t)col * GSZ;
    for (int t = threadIdx.x; t < GSZ; t += 256) {
        float2 v = s[t];
        outp[t] = make_float2(v.x * scale, v.y * scale);
    }
}

// ---------------------------------------------------------------------------
// Kernel 4: KB gridding gather over HALF the detectors (d = 0..384).
// The real grid makes the spectrum Hermitian; detector 768-d samples -k of
// detector d, and by KB weight/index mirror symmetry its gather equals the
// conjugate. Scatter conj(val) to the mirror slot.
// ---------------------------------------------------------------------------
__global__ void gather_kernel(const float* __restrict__ ksp) {
    int p = blockIdx.x * blockDim.x + threadIdx.x;
    if (p >= NANG * NDHALF) return;
    int a = p / NDHALF;
    int d = p - a * NDHALF;
    int po = a * NDET + d;               // original point index

    const float c = (float)GSZ / TWO_PI;
    float g1 = fmodf(ksp[po] * c, (float)GSZ);          if (g1 < 0.0f) g1 += (float)GSZ;
    float g2 = fmodf(ksp[KPTS + po] * c, (float)GSZ);   if (g2 < 0.0f) g2 += (float)GSZ;

    int b1 = (int)floorf(g1);
    int b2 = (int)floorf(g2);

    float inv_i0a = 1.0f / i0f_dev(ALPHA_C);   // cancels against apodization's i0a
    float wx[JW], wy[JW];
    #pragma unroll
    for (int j = 0; j < JW; ++j) {
        float u = g1 - (float)(b1 - 2 + j);
        float xx = fmaxf(fmaf(-u * u, (1.0f / 9.0f), 1.0f), 0.0f);
        wx[j] = i0_alpha_sqrt(xx) * inv_i0a;
        float v = g2 - (float)(b2 - 2 + j);
        float yy = fmaxf(fmaf(-v * v, (1.0f / 9.0f), 1.0f), 0.0f);
        wy[j] = i0_alpha_sqrt(yy) * inv_i0a;
    }

    float accx = 0.0f, accy = 0.0f;

    if (b1 >= 2 && b1 <= 1018 && b2 >= 2 && b2 <= 1020) {
        int ix0 = b1 - 2;
        int a0  = ix0 & ~1;        // float4-aligned base (float2 units)
        int off = ix0 & 1;
        float w0 = off ? 0.0f  : wx[0];
        float w1 = off ? wx[0] : wx[1];
        float w2 = off ? wx[1] : wx[2];
        float w3 = off ? wx[2] : wx[3];
        float w4 = off ? wx[3] : wx[4];
        float w5 = off ? wx[4] : wx[5];
        float w6 = off ? wx[5] : 0.0f;
        const float4* base = (const float4*)(g_specT + ((size_t)(b2 - 2) * GSZ + a0));
        #pragma unroll
        for (int bb = 0; bb < JW; ++bb) {
            const float4* rp = base + (size_t)bb * (GSZ / 2);
            float4 v0 = __ldg(rp);
            float4 v1 = __ldg(rp + 1);
            float4 v2 = __ldg(rp + 2);
            float4 v3 = __ldg(rp + 3);
            float px = v0.x * w0;
            float py = v0.y * w0;
            px = fmaf(v0.z, w1, px);  py = fmaf(v0.w, w1, py);
            px = fmaf(v1.x, w2, px);  py = fmaf(v1.y, w2, py);
            px = fmaf(v1.z, w3, px);  py = fmaf(v1.w, w3, py);
            px = fmaf(v2.x, w4, px);  py = fmaf(v2.y, w4, py);
            px = fmaf(v2.z, w5, px);  py = fmaf(v2.w, w5, py);
            px = fmaf(v3.x, w6, px);  py = fmaf(v3.y, w6, py);
            accx = fmaf(px, wy[bb], accx);
            accy = fmaf(py, wy[bb], accy);
        }
    } else {
        int ix[JW], iy[JW];
        #pragma unroll
        for (int j = 0; j < JW; ++j) {
            ix[j] = (b1 - 2 + j + GSZ) & (GSZ - 1);
            iy[j] = (b2 - 2 + j + GSZ) & (GSZ - 1);
        }
        #pragma unroll
        for (int bb = 0; bb < JW; ++bb) {
            const float2* __restrict__ rowp = g_specT + (size_t)iy[bb] * GSZ;
            float px = 0.0f, py = 0.0f;
            #pragma unroll
            for (int aa = 0; aa < JW; ++aa) {
                float2 v = __ldg(&rowp[ix[aa]]);
                px = fmaf(v.x, wx[aa], px);
                py = fmaf(v.y, wx[aa], py);
            }
            accx = fmaf(px, wy[bb], accx);
            accy = fmaf(py, wy[bb], accy);
        }
    }

    g_kdata[po] = make_float2(accx, accy);
    if (d > 0 && d < 384) {
        g_kdata[a * NDET + (NDET - d)] = make_float2(accx, -accy);  // conj @ mirror
    }
}

// ---------------------------------------------------------------------------
// Kernel 5: per-angle 768-pt inverse FFT (3 x 256 mixed radix), shifts folded.
// ---------------------------------------------------------------------------
__global__ void ifft768_kernel(float* __restrict__ out) {
    __shared__ float2 sY[3][256];
    int a = blockIdx.x;
    const float2* rowin = g_kdata + (size_t)a * NDET;

    int r = threadIdx.x >> 7;
    int lt = threadIdx.x & 127;

    for (int m = lt; m < 256; m += 128) {
        int src = (3 * m + r + 384) % NDET;
        sY[r][__brev(m) >> 24] = rowin[src];
    }
    __syncthreads();

    #pragma unroll
    for (int st = 0; st < 8; ++st) {
        int half = 1 << st;
        int len = half << 1;
        int grp = lt >> st;
        int pos = lt & (half - 1);
        int ii = grp * len + pos;
        int kk = ii + half;
        float ang = TWO_PI * (float)pos / (float)len;
        float sw, cw;
        __sincosf(ang, &sw, &cw);
        float2 b = sY[r][kk];
        float2 wb = make_float2(b.x * cw - b.y * sw, b.x * sw + b.y * cw);
        float2 aa = sY[r][ii];
        sY[r][ii] = make_float2(aa.x + wb.x, aa.y + wb.y);
        sY[r][kk] = make_float2(aa.x - wb.x, aa.y - wb.y);
        __syncthreads();
    }

    const float inv = 1.0f / 768.0f;
    for (int k = threadIdx.x; k < NDET; k += 384) {
        int k0 = k & 255;
        float re = sY[0][k0].x;
        float a1 = TWO_PI * (float)k * (1.0f / 768.0f);
        float s1, c1;
        __sincosf(a1, &s1, &c1);
        re += sY[1][k0].x * c1 - sY[1][k0].y * s1;
        float s2, c2;
        __sincosf(a1 + a1, &s2, &c2);
        re += sY[2][k0].x * c2 - sY[2][k0].y * s2;
        out[(size_t)a * NDET + ((k + 384) % NDET)] = re * inv;
    }
}

// ---------------------------------------------------------------------------
extern "C" void kernel_launch(void* const* d_in, const int* in_sizes, int n_in,
                              void* d_out, int out_size) {
    const float* img = (const float*)d_in[0];
    const float* ksp = (const float*)d_in[1];
    float* out = (float*)d_out;

    build_grid_kernel<<<dim3(GSZ / 256, GSZ), 256>>>(img);
    fft_rows_kernel<<<512, 256>>>();
    fft_cols_kernel<<<GSZ, 256>>>();
    gather_kernel<<<(NANG * NDHALF + 255) / 256, 256>>>(ksp);
    ifft768_kernel<<<NANG, 384>>>(out);
}

// round 5
// speedup vs baseline: 1.3879x; 1.0571x over previous
#include <cuda_runtime.h>
#include <math.h>

#define JW 6
#define ALPHA_C 14.04f            // 2.34 * J
#define GSZ 1024                  // G1 == G2 == 2*H
#define NANG 720
#define NDET 768
#define KPTS (NANG * NDET)
#define NDHALF 385                // detectors gathered: d = 0..384 (Hermitian)
#define TWO_PI 6.283185307179586f

__device__ float2 g_grid[GSZ * GSZ];   // row-FFT'd padded image (zero rows never touched/read)
__device__ float2 g_specT[GSZ * GSZ];  // transposed spectrum: specT[j][i] = FFT2[i][j]/1024

// ---------------------------------------------------------------------------
// I0 (A&S) — normalizer; cancels against apodization's I0(alpha).
// ---------------------------------------------------------------------------
__device__ __forceinline__ float i0f_dev(float z) {
    if (z < 3.75f) {
        float t = z * (1.0f / 3.75f);
        float t2 = t * t;
        return 1.0f + t2 * (3.5156229f + t2 * (3.0899424f + t2 * (1.2067492f
                     + t2 * (0.2659732f + t2 * (0.0360768f + t2 * 0.0045813f)))));
    } else {
        float ti = 3.75f / z;
        float p = 0.39894228f + ti * (0.01328592f + ti * (0.00225319f
                + ti * (-0.00157565f + ti * (0.00916281f + ti * (-0.02057706f
                + ti * (0.02635537f + ti * (-0.01647633f + ti * 0.00392377f)))))));
        return p * __expf(z) * rsqrtf(z);
    }
}

// I0(alpha*sqrt(x)) on [0,1]: pure-FMA power series in x (k=16).
__device__ __forceinline__ float i0_alpha_sqrt(float x) {
    float s;
    s = 2.764070f;
    s = fmaf(s, x, 14.35870f);
    s = fmaf(s, x, 65.55800f);
    s = fmaf(s, x, 260.7380f);
    s = fmaf(s, x, 894.1610f);
    s = fmaf(s, x, 2612.787f);
    s = fmaf(s, x, 6415.273f);
    s = fmaf(s, x, 13017.90f);
    s = fmaf(s, x, 21396.99f);
    s = fmaf(s, x, 27788.08f);
    s = fmaf(s, x, 27629.97f);
    s = fmaf(s, x, 20184.07f);
    s = fmaf(s, x, 10239.40f);
    s = fmaf(s, x, 3324.453f);
    s = fmaf(s, x, 607.1395f);
    s = fmaf(s, x, 49.28040f);
    s = fmaf(s, x, 1.0f);
    return s;
}

__device__ __forceinline__ float apod_val(int n, float i0a) {
    float u = (float)(n - 256) * (1.0f / (float)GSZ);
    float t = 3.14159265358979f * (float)JW * u;
    float arg = ALPHA_C * ALPHA_C - t * t;
    float s = sqrtf(fabsf(arg) + 1e-20f);
    float sh;
    if (arg > 0.0f) {
        float e = __expf(s);
        sh = 0.5f * (e - 1.0f / e);
    } else {
        sh = __sinf(s);
    }
    float F = (sh / s) * ((float)JW / i0a);
    return 1.0f / F;
}

// ---------------------------------------------------------------------------
// Shared-memory radix-2 FFT stages (input in bit-reversed order).
// ---------------------------------------------------------------------------
__device__ __forceinline__ void fft_stages_1024(float2* s, float sign) {
    #pragma unroll
    for (int st = 0; st < 10; ++st) {
        int half = 1 << st;
        int len = half << 1;
        #pragma unroll
        for (int q = 0; q < 2; ++q) {
            int t = threadIdx.x + q * 256;
            int grp = t >> st;
            int pos = t & (half - 1);
            int ii = grp * len + pos;
            int kk = ii + half;
            float ang = sign * TWO_PI * (float)pos / (float)len;
            float sw, cw;
            __sincosf(ang, &sw, &cw);
            float2 b = s[kk];
            float2 wb = make_float2(b.x * cw - b.y * sw, b.x * sw + b.y * cw);
            float2 a = s[ii];
            s[ii] = make_float2(a.x + wb.x, a.y + wb.y);
            s[kk] = make_float2(a.x - wb.x, a.y - wb.y);
        }
        __syncthreads();
    }
}

// ---------------------------------------------------------------------------
// Kernel 1 (fused): apodize + pad + ifftshift + row FFT, nonzero rows only.
// Block b handles shifted row: b<256 -> row b (source ri=b+256),
// b>=256 -> row b+512 (source ri=b-256).
// ---------------------------------------------------------------------------
__global__ void build_fft_rows_kernel(const float* __restrict__ img) {
    __shared__ float2 s[GSZ];
    int b = blockIdx.x;
    int row = (b < 256) ? b : (b + 512);
    int ri  = (b < 256) ? (b + 256) : (b - 256);

    float i0a = i0f_dev(ALPHA_C);
    float arow = apod_val(ri, i0a);
    const float* imrow = img + ri * 512;

    // Columns: j in [0,256) -> ci = j+256 ; j in [768,1024) -> ci = j-768+0
    for (int q = 0; q < 4; ++q) {
        int j = threadIdx.x + q * 256;
        float2 v = make_float2(0.0f, 0.0f);
        if (q == 0) {
            int ci = j + 256;
            v.x = imrow[ci] * arow * apod_val(ci, i0a);
        } else if (q == 3) {
            int ci = j - 768;
            v.x = imrow[ci] * arow * apod_val(ci, i0a);
        }
        s[__brev(j) >> 22] = v;
    }
    __syncthreads();
    fft_stages_1024(s, -1.0f);
    float2* base = g_grid + (size_t)row * GSZ;
    for (int t = threadIdx.x; t < GSZ; t += 256) {
        base[t] = s[t];
    }
}

// ---------------------------------------------------------------------------
// Kernel 2: column FFT; rows [256,768) are known-zero -> no loads for them.
// Writes transposed + normalized spectrum.
// ---------------------------------------------------------------------------
__global__ void fft_cols_kernel() {
    __shared__ float2 s[GSZ];
    int col = blockIdx.x;
    {
        int t0 = threadIdx.x;            // nonzero
        int t3 = threadIdx.x + 768;      // nonzero
        s[__brev(t0) >> 22] = g_grid[(size_t)t0 * GSZ + col];
        s[__brev(threadIdx.x + 256) >> 22] = make_float2(0.0f, 0.0f);
        s[__brev(threadIdx.x + 512) >> 22] = make_float2(0.0f, 0.0f);
        s[__brev(t3) >> 22] = g_grid[(size_t)t3 * GSZ + col];
    }
    __syncthreads();
    fft_stages_1024(s, -1.0f);
    const float scale = 1.0f / 1024.0f;
    float2* outp = g_specT + (size_t)col * GSZ;
    for (int t = threadIdx.x; t < GSZ; t += 256) {
        float2 v = s[t];
        outp[t] = make_float2(v.x * scale, v.y * scale);
    }
}

// ---------------------------------------------------------------------------
// Kernel 3 (fused): KB gather (half detectors, Hermitian mirror in smem)
// + per-angle 768-pt inverse FFT. One block per angle, 384 threads.
// ---------------------------------------------------------------------------
__global__ void gather_ifft_kernel(const float* __restrict__ ksp,
                                   float* __restrict__ out) {
    __shared__ float2 kd[NDET];
    __shared__ float2 sY[3][256];
    int a = blockIdx.x;

    float inv_i0a = 1.0f / i0f_dev(ALPHA_C);
    const float c = (float)GSZ / TWO_PI;

    // ---- Gather phase: d = tid (all), plus d = 384 handled by tid 0 ----
    for (int d = threadIdx.x; d < NDHALF; d += 384) {
        int po = a * NDET + d;
        float g1 = fmodf(ksp[po] * c, (float)GSZ);          if (g1 < 0.0f) g1 += (float)GSZ;
        float g2 = fmodf(ksp[KPTS + po] * c, (float)GSZ);   if (g2 < 0.0f) g2 += (float)GSZ;

        int b1 = (int)floorf(g1);
        int b2 = (int)floorf(g2);

        float wx[JW], wy[JW];
        #pragma unroll
        for (int j = 0; j < JW; ++j) {
            float u = g1 - (float)(b1 - 2 + j);
            float xx = fmaxf(fmaf(-u * u, (1.0f / 9.0f), 1.0f), 0.0f);
            wx[j] = i0_alpha_sqrt(xx) * inv_i0a;
            float v = g2 - (float)(b2 - 2 + j);
            float yy = fmaxf(fmaf(-v * v, (1.0f / 9.0f), 1.0f), 0.0f);
            wy[j] = i0_alpha_sqrt(yy) * inv_i0a;
        }

        float accx = 0.0f, accy = 0.0f;

        if (b1 >= 2 && b1 <= 1018 && b2 >= 2 && b2 <= 1020) {
            int ix0 = b1 - 2;
            int a0  = ix0 & ~1;
            int off = ix0 & 1;
            float w0 = off ? 0.0f  : wx[0];
            float w1 = off ? wx[0] : wx[1];
            float w2 = off ? wx[1] : wx[2];
            float w3 = off ? wx[2] : wx[3];
            float w4 = off ? wx[3] : wx[4];
            float w5 = off ? wx[4] : wx[5];
            float w6 = off ? wx[5] : 0.0f;
            const float4* base = (const float4*)(g_specT + ((size_t)(b2 - 2) * GSZ + a0));
            #pragma unroll
            for (int bb = 0; bb < JW; ++bb) {
                const float4* rp = base + (size_t)bb * (GSZ / 2);
                float4 v0 = __ldg(rp);
                float4 v1 = __ldg(rp + 1);
                float4 v2 = __ldg(rp + 2);
                float4 v3 = __ldg(rp + 3);
                float px = v0.x * w0;
                float py = v0.y * w0;
                px = fmaf(v0.z, w1, px);  py = fmaf(v0.w, w1, py);
                px = fmaf(v1.x, w2, px);  py = fmaf(v1.y, w2, py);
                px = fmaf(v1.z, w3, px);  py = fmaf(v1.w, w3, py);
                px = fmaf(v2.x, w4, px);  py = fmaf(v2.y, w4, py);
                px = fmaf(v2.z, w5, px);  py = fmaf(v2.w, w5, py);
                px = fmaf(v3.x, w6, px);  py = fmaf(v3.y, w6, py);
                accx = fmaf(px, wy[bb], accx);
                accy = fmaf(py, wy[bb], accy);
            }
        } else {
            int ix[JW], iy[JW];
            #pragma unroll
            for (int j = 0; j < JW; ++j) {
                ix[j] = (b1 - 2 + j + GSZ) & (GSZ - 1);
                iy[j] = (b2 - 2 + j + GSZ) & (GSZ - 1);
            }
            #pragma unroll
            for (int bb = 0; bb < JW; ++bb) {
                const float2* __restrict__ rowp = g_specT + (size_t)iy[bb] * GSZ;
                float px = 0.0f, py = 0.0f;
                #pragma unroll
                for (int aa = 0; aa < JW; ++aa) {
                    float2 v = __ldg(&rowp[ix[aa]]);
                    px = fmaf(v.x, wx[aa], px);
                    py = fmaf(v.y, wx[aa], py);
                }
                accx = fmaf(px, wy[bb], accx);
                accy = fmaf(py, wy[bb], accy);
            }
        }

        kd[d] = make_float2(accx, accy);
        if (d > 0 && d < 384) {
            kd[NDET - d] = make_float2(accx, -accy);   // Hermitian mirror
        }
    }
    __syncthreads();

    // ---- IFFT phase: 768 = 3 x 256 mixed radix; shifts folded into indices ----
    int r = threadIdx.x >> 7;
    int lt = threadIdx.x & 127;

    for (int m = lt; m < 256; m += 128) {
        int src = (3 * m + r + 384) % NDET;
        sY[r][__brev(m) >> 24] = kd[src];
    }
    __syncthreads();

    #pragma unroll
    for (int st = 0; st < 8; ++st) {
        int half = 1 << st;
        int len = half << 1;
        int grp = lt >> st;
        int pos = lt & (half - 1);
        int ii = grp * len + pos;
        int kk = ii + half;
        float ang = TWO_PI * (float)pos / (float)len;
        float sw, cw;
        __sincosf(ang, &sw, &cw);
        float2 b = sY[r][kk];
        float2 wb = make_float2(b.x * cw - b.y * sw, b.x * sw + b.y * cw);
        float2 aa = sY[r][ii];
        sY[r][ii] = make_float2(aa.x + wb.x, aa.y + wb.y);
        sY[r][kk] = make_float2(aa.x - wb.x, aa.y - wb.y);
        __syncthreads();
    }

    const float inv = 1.0f / 768.0f;
    for (int k = threadIdx.x; k < NDET; k += 384) {
        int k0 = k & 255;
        float re = sY[0][k0].x;
        float a1 = TWO_PI * (float)k * (1.0f / 768.0f);
        float s1, c1;
        __sincosf(a1, &s1, &c1);
        re += sY[1][k0].x * c1 - sY[1][k0].y * s1;
        float s2, c2;
        __sincosf(a1 + a1, &s2, &c2);
        re += sY[2][k0].x * c2 - sY[2][k0].y * s2;
        out[(size_t)a * NDET + ((k + 384) % NDET)] = re * inv;
    }
}

// ---------------------------------------------------------------------------
extern "C" void kernel_launch(void* const* d_in, const int* in_sizes, int n_in,
                              void* d_out, int out_size) {
    const float* img = (const float*)d_in[0];
    const float* ksp = (const float*)d_in[1];
    float* out = (float*)d_out;

    build_fft_rows_kernel<<<512, 256>>>(img);
    fft_cols_kernel<<<GSZ, 256>>>();
    gather_ifft_kernel<<<NANG, 384>>>(ksp, out);
}

// round 6
// speedup vs baseline: 1.5276x; 1.1006x over previous
#include <cuda_runtime.h>
#include <math.h>

#define JW 6
#define ALPHA_C 14.04f            // 2.34 * J
#define GSZ 1024                  // G1 == G2 == 2*H
#define NANG 720
#define NDET 768
#define KPTS (NANG * NDET)
#define NDHALF 385                // detectors gathered: d = 0..384 (Hermitian)
#define TWO_PI 6.283185307179586f

__device__ float2 g_grid[GSZ * GSZ];   // row-FFT'd padded image (zero rows never touched/read)
__device__ float2 g_specT[GSZ * GSZ];  // transposed spectrum: specT[j][i] = FFT2[i][j]/1024

// ---------------------------------------------------------------------------
// I0 (A&S) — normalizer; cancels against apodization's I0(alpha).
// ---------------------------------------------------------------------------
__device__ __forceinline__ float i0f_dev(float z) {
    if (z < 3.75f) {
        float t = z * (1.0f / 3.75f);
        float t2 = t * t;
        return 1.0f + t2 * (3.5156229f + t2 * (3.0899424f + t2 * (1.2067492f
                     + t2 * (0.2659732f + t2 * (0.0360768f + t2 * 0.0045813f)))));
    } else {
        float ti = 3.75f / z;
        float p = 0.39894228f + ti * (0.01328592f + ti * (0.00225319f
                + ti * (-0.00157565f + ti * (0.00916281f + ti * (-0.02057706f
                + ti * (0.02635537f + ti * (-0.01647633f + ti * 0.00392377f)))))));
        return p * __expf(z) * rsqrtf(z);
    }
}

// I0(alpha*sqrt(x)) on [0,1]: pure-FMA power series in x (k=16).
__device__ __forceinline__ float i0_alpha_sqrt(float x) {
    float s;
    s = 2.764070f;
    s = fmaf(s, x, 14.35870f);
    s = fmaf(s, x, 65.55800f);
    s = fmaf(s, x, 260.7380f);
    s = fmaf(s, x, 894.1610f);
    s = fmaf(s, x, 2612.787f);
    s = fmaf(s, x, 6415.273f);
    s = fmaf(s, x, 13017.90f);
    s = fmaf(s, x, 21396.99f);
    s = fmaf(s, x, 27788.08f);
    s = fmaf(s, x, 27629.97f);
    s = fmaf(s, x, 20184.07f);
    s = fmaf(s, x, 10239.40f);
    s = fmaf(s, x, 3324.453f);
    s = fmaf(s, x, 607.1395f);
    s = fmaf(s, x, 49.28040f);
    s = fmaf(s, x, 1.0f);
    return s;
}

__device__ __forceinline__ float apod_val(int n, float i0a) {
    float u = (float)(n - 256) * (1.0f / (float)GSZ);
    float t = 3.14159265358979f * (float)JW * u;
    float arg = ALPHA_C * ALPHA_C - t * t;
    float s = sqrtf(fabsf(arg) + 1e-20f);
    float sh;
    if (arg > 0.0f) {
        float e = __expf(s);
        sh = 0.5f * (e - 1.0f / e);
    } else {
        sh = __sinf(s);
    }
    float F = (sh / s) * ((float)JW / i0a);
    return 1.0f / F;
}

// Base-4 digit reversal of a 10-bit index (1024 = 4^5).
__device__ __forceinline__ int rev4_10(int t) {
    int x = __brev(t) >> 22;                       // 10-bit bit reversal
    return ((x & 0x155) << 1) | ((x >> 1) & 0x155); // swap adjacent bit pairs
}

// ---------------------------------------------------------------------------
// Radix-4 1024-pt FFT on smem, 256 threads, input in base-4-digit-reversed
// order, output natural. sign=-1 forward, +1 inverse (unnormalized).
// ---------------------------------------------------------------------------
__device__ __forceinline__ void fft1024_r4(float2* s, float sign) {
    #pragma unroll
    for (int st = 0; st < 5; ++st) {
        int Q = 1 << (2 * st);
        int t = threadIdx.x;
        int g = t >> (2 * st);
        int p = t & (Q - 1);
        int base = g * (Q << 2) + p;
        float ang = sign * TWO_PI * (float)p / (float)(Q << 2);
        float s1, c1;
        __sincosf(ang, &s1, &c1);
        float c2 = c1 * c1 - s1 * s1, s2 = 2.0f * c1 * s1;     // w^2
        float c3 = c1 * c2 - s1 * s2, s3 = c1 * s2 + s1 * c2;  // w^3
        float2 x0 = s[base];
        float2 x1 = s[base + Q];
        float2 x2 = s[base + 2 * Q];
        float2 x3 = s[base + 3 * Q];
        float2 t1 = make_float2(x1.x * c1 - x1.y * s1, x1.x * s1 + x1.y * c1);
        float2 t2 = make_float2(x2.x * c2 - x2.y * s2, x2.x * s2 + x2.y * c2);
        float2 t3 = make_float2(x3.x * c3 - x3.y * s3, x3.x * s3 + x3.y * c3);
        float2 u0 = make_float2(x0.x + t2.x, x0.y + t2.y);
        float2 u1 = make_float2(x0.x - t2.x, x0.y - t2.y);
        float2 u2 = make_float2(t1.x + t3.x, t1.y + t3.y);
        float2 u3 = make_float2(t1.x - t3.x, t1.y - t3.y);
        float2 v  = make_float2(-u3.y, u3.x);                  // i*u3
        s[base]         = make_float2(u0.x + u2.x, u0.y + u2.y);
        s[base + 2 * Q] = make_float2(u0.x - u2.x, u0.y - u2.y);
        s[base + Q]     = make_float2(u1.x + sign * v.x, u1.y + sign * v.y);
        s[base + 3 * Q] = make_float2(u1.x - sign * v.x, u1.y - sign * v.y);
        __syncthreads();
    }
}

// ---------------------------------------------------------------------------
// Kernel 1: apodize + pad + ifftshift + row FFT, TWO real rows packed per
// complex FFT. Block b: shifted row b (source b+256) packed with shifted
// row b+768 (source b). 256 blocks.
// ---------------------------------------------------------------------------
__global__ void build_fft_rows_kernel(const float* __restrict__ img) {
    __shared__ float2 s[GSZ];
    int b = blockIdx.x;
    float i0a = i0f_dev(ALPHA_C);
    float aA = apod_val(b + 256, i0a);     // row factor for shifted row b
    float aB = apod_val(b, i0a);           // row factor for shifted row b+768
    const float* imA = img + (b + 256) * 512;
    const float* imB = img + b * 512;

    // shifted col j: source ci = j+256 (j<256) or j-768 (j>=768), else zero
    #pragma unroll
    for (int q = 0; q < 4; ++q) {
        int j = threadIdx.x + q * 256;
        float2 z = make_float2(0.0f, 0.0f);
        if (q == 0) {
            int ci = j + 256;
            float ac = apod_val(ci, i0a);
            z.x = imA[ci] * aA * ac;
            z.y = imB[ci] * aB * ac;
        } else if (q == 3) {
            int ci = j - 768;
            float ac = apod_val(ci, i0a);
            z.x = imA[ci] * aA * ac;
            z.y = imB[ci] * aB * ac;
        }
        s[rev4_10(j)] = z;
    }
    __syncthreads();
    fft1024_r4(s, -1.0f);

    // Unpack Hermitian split and store both rows.
    float2* baseA = g_grid + (size_t)b * GSZ;
    float2* baseB = g_grid + (size_t)(b + 768) * GSZ;
    #pragma unroll
    for (int q = 0; q < 4; ++q) {
        int k = threadIdx.x + q * 256;
        float2 Zk = s[k];
        float2 Zn = s[(GSZ - k) & (GSZ - 1)];
        baseA[k] = make_float2(0.5f * (Zk.x + Zn.x), 0.5f * (Zk.y - Zn.y));
        baseB[k] = make_float2(0.5f * (Zk.y + Zn.y), 0.5f * (Zn.x - Zk.x));
    }
}

// ---------------------------------------------------------------------------
// Kernel 2: column FFT (radix-4); rows [256,768) known-zero -> no loads.
// Writes transposed + normalized spectrum.
// ---------------------------------------------------------------------------
__global__ void fft_cols_kernel() {
    __shared__ float2 s[GSZ];
    int col = blockIdx.x;
    {
        int t0 = threadIdx.x;
        int t3 = threadIdx.x + 768;
        s[rev4_10(t0)] = g_grid[(size_t)t0 * GSZ + col];
        s[rev4_10(threadIdx.x + 256)] = make_float2(0.0f, 0.0f);
        s[rev4_10(threadIdx.x + 512)] = make_float2(0.0f, 0.0f);
        s[rev4_10(t3)] = g_grid[(size_t)t3 * GSZ + col];
    }
    __syncthreads();
    fft1024_r4(s, -1.0f);
    const float scale = 1.0f / 1024.0f;
    float2* outp = g_specT + (size_t)col * GSZ;
    #pragma unroll
    for (int q = 0; q < 4; ++q) {
        int t = threadIdx.x + q * 256;
        float2 v = s[t];
        outp[t] = make_float2(v.x * scale, v.y * scale);
    }
}

// ---------------------------------------------------------------------------
// Kernel 3 (fused): KB gather (half detectors, Hermitian mirror in smem)
// + per-angle 768-pt inverse FFT. One block per angle, 384 threads.
// ---------------------------------------------------------------------------
__global__ void gather_ifft_kernel(const float* __restrict__ ksp,
                                   float* __restrict__ out) {
    __shared__ float2 kd[NDET];
    __shared__ float2 sY[3][256];
    int a = blockIdx.x;

    float inv_i0a = 1.0f / i0f_dev(ALPHA_C);
    const float c = (float)GSZ / TWO_PI;

    for (int d = threadIdx.x; d < NDHALF; d += 384) {
        int po = a * NDET + d;
        float g1 = fmodf(ksp[po] * c, (float)GSZ);          if (g1 < 0.0f) g1 += (float)GSZ;
        float g2 = fmodf(ksp[KPTS + po] * c, (float)GSZ);   if (g2 < 0.0f) g2 += (float)GSZ;

        int b1 = (int)floorf(g1);
        int b2 = (int)floorf(g2);

        float wx[JW], wy[JW];
        #pragma unroll
        for (int j = 0; j < JW; ++j) {
            float u = g1 - (float)(b1 - 2 + j);
            float xx = fmaxf(fmaf(-u * u, (1.0f / 9.0f), 1.0f), 0.0f);
            wx[j] = i0_alpha_sqrt(xx) * inv_i0a;
            float v = g2 - (float)(b2 - 2 + j);
            float yy = fmaxf(fmaf(-v * v, (1.0f / 9.0f), 1.0f), 0.0f);
            wy[j] = i0_alpha_sqrt(yy) * inv_i0a;
        }

        float accx = 0.0f, accy = 0.0f;

        if (b1 >= 2 && b1 <= 1018 && b2 >= 2 && b2 <= 1020) {
            int ix0 = b1 - 2;
            int a0  = ix0 & ~1;
            int off = ix0 & 1;
            float w0 = off ? 0.0f  : wx[0];
            float w1 = off ? wx[0] : wx[1];
            float w2 = off ? wx[1] : wx[2];
            float w3 = off ? wx[2] : wx[3];
            float w4 = off ? wx[3] : wx[4];
            float w5 = off ? wx[4] : wx[5];
            float w6 = off ? wx[5] : 0.0f;
            const float4* base = (const float4*)(g_specT + ((size_t)(b2 - 2) * GSZ + a0));
            #pragma unroll
            for (int bb = 0; bb < JW; ++bb) {
                const float4* rp = base + (size_t)bb * (GSZ / 2);
                float4 v0 = __ldg(rp);
                float4 v1 = __ldg(rp + 1);
                float4 v2 = __ldg(rp + 2);
                float4 v3 = __ldg(rp + 3);
                float px = v0.x * w0;
                float py = v0.y * w0;
                px = fmaf(v0.z, w1, px);  py = fmaf(v0.w, w1, py);
                px = fmaf(v1.x, w2, px);  py = fmaf(v1.y, w2, py);
                px = fmaf(v1.z, w3, px);  py = fmaf(v1.w, w3, py);
                px = fmaf(v2.x, w4, px);  py = fmaf(v2.y, w4, py);
                px = fmaf(v2.z, w5, px);  py = fmaf(v2.w, w5, py);
                px = fmaf(v3.x, w6, px);  py = fmaf(v3.y, w6, py);
                accx = fmaf(px, wy[bb], accx);
                accy = fmaf(py, wy[bb], accy);
            }
        } else {
            int ix[JW], iy[JW];
            #pragma unroll
            for (int j = 0; j < JW; ++j) {
                ix[j] = (b1 - 2 + j + GSZ) & (GSZ - 1);
                iy[j] = (b2 - 2 + j + GSZ) & (GSZ - 1);
            }
            #pragma unroll
            for (int bb = 0; bb < JW; ++bb) {
                const float2* __restrict__ rowp = g_specT + (size_t)iy[bb] * GSZ;
                float px = 0.0f, py = 0.0f;
                #pragma unroll
                for (int aa = 0; aa < JW; ++aa) {
                    float2 v = __ldg(&rowp[ix[aa]]);
                    px = fmaf(v.x, wx[aa], px);
                    py = fmaf(v.y, wx[aa], py);
                }
                accx = fmaf(px, wy[bb], accx);
                accy = fmaf(py, wy[bb], accy);
            }
        }

        kd[d] = make_float2(accx, accy);
        if (d > 0 && d < 384) {
            kd[NDET - d] = make_float2(accx, -accy);   // Hermitian mirror
        }
    }
    __syncthreads();

    // ---- IFFT: 768 = 3 x 256 mixed radix; shifts folded into indices ----
    int r = threadIdx.x >> 7;
    int lt = threadIdx.x & 127;

    for (int m = lt; m < 256; m += 128) {
        int src = (3 * m + r + 384) % NDET;
        sY[r][__brev(m) >> 24] = kd[src];
    }
    __syncthreads();

    #pragma unroll
    for (int st = 0; st < 8; ++st) {
        int half = 1 << st;
        int len = half << 1;
        int grp = lt >> st;
        int pos = lt & (half - 1);
        int ii = grp * len + pos;
        int kk = ii + half;
        float ang = TWO_PI * (float)pos / (float)len;
        float sw, cw;
        __sincosf(ang, &sw, &cw);
        float2 b = sY[r][kk];
        float2 wb = make_float2(b.x * cw - b.y * sw, b.x * sw + b.y * cw);
        float2 aa = sY[r][ii];
        sY[r][ii] = make_float2(aa.x + wb.x, aa.y + wb.y);
        sY[r][kk] = make_float2(aa.x - wb.x, aa.y - wb.y);
        __syncthreads();
    }

    const float inv = 1.0f / 768.0f;
    for (int k = threadIdx.x; k < NDET; k += 384) {
        int k0 = k & 255;
        float re = sY[0][k0].x;
        float a1 = TWO_PI * (float)k * (1.0f / 768.0f);
        float s1, c1;
        __sincosf(a1, &s1, &c1);
        re += sY[1][k0].x * c1 - sY[1][k0].y * s1;
        float s2, c2;
        __sincosf(a1 + a1, &s2, &c2);
        re += sY[2][k0].x * c2 - sY[2][k0].y * s2;
        out[(size_t)a * NDET + ((k + 384) % NDET)] = re * inv;
    }
}

// ---------------------------------------------------------------------------
extern "C" void kernel_launch(void* const* d_in, const int* in_sizes, int n_in,
                              void* d_out, int out_size) {
    const float* img = (const float*)d_in[0];
    const float* ksp = (const float*)d_in[1];
    float* out = (float*)d_out;

    build_fft_rows_kernel<<<256, 256>>>(img);
    fft_cols_kernel<<<GSZ, 256>>>();
    gather_ifft_kernel<<<NANG, 384>>>(ksp, out);
}

// round 7
// speedup vs baseline: 1.6058x; 1.0512x over previous
#include <cuda_runtime.h>
#include <math.h>

#define JW 6
#define ALPHA_C 14.04f            // 2.34 * J
#define GSZ 1024                  // G1 == G2 == 2*H
#define NANG 720
#define NDET 768
#define KPTS (NANG * NDET)
#define NDHALF 385                // detectors gathered: d = 0..384 (Hermitian in detector dim)
#define TWO_PI 6.283185307179586f

__device__ float2 g_grid[GSZ * GSZ];          // row-FFT'd padded image (zero rows untouched)
__device__ float2 g_specT[513 * GSZ];         // HALF spectrum: rows j=0..512, specT[j][i]=FFT2[i][j]/1024

// ---------------------------------------------------------------------------
// I0 (A&S) — normalizer; cancels against apodization's I0(alpha).
// ---------------------------------------------------------------------------
__device__ __forceinline__ float i0f_dev(float z) {
    if (z < 3.75f) {
        float t = z * (1.0f / 3.75f);
        float t2 = t * t;
        return 1.0f + t2 * (3.5156229f + t2 * (3.0899424f + t2 * (1.2067492f
                     + t2 * (0.2659732f + t2 * (0.0360768f + t2 * 0.0045813f)))));
    } else {
        float ti = 3.75f / z;
        float p = 0.39894228f + ti * (0.01328592f + ti * (0.00225319f
                + ti * (-0.00157565f + ti * (0.00916281f + ti * (-0.02057706f
                + ti * (0.02635537f + ti * (-0.01647633f + ti * 0.00392377f)))))));
        return p * __expf(z) * rsqrtf(z);
    }
}

// I0(alpha*sqrt(x)) on [0,1]: pure-FMA power series in x (k=16).
__device__ __forceinline__ float i0_alpha_sqrt(float x) {
    float s;
    s = 2.764070f;
    s = fmaf(s, x, 14.35870f);
    s = fmaf(s, x, 65.55800f);
    s = fmaf(s, x, 260.7380f);
    s = fmaf(s, x, 894.1610f);
    s = fmaf(s, x, 2612.787f);
    s = fmaf(s, x, 6415.273f);
    s = fmaf(s, x, 13017.90f);
    s = fmaf(s, x, 21396.99f);
    s = fmaf(s, x, 27788.08f);
    s = fmaf(s, x, 27629.97f);
    s = fmaf(s, x, 20184.07f);
    s = fmaf(s, x, 10239.40f);
    s = fmaf(s, x, 3324.453f);
    s = fmaf(s, x, 607.1395f);
    s = fmaf(s, x, 49.28040f);
    s = fmaf(s, x, 1.0f);
    return s;
}

__device__ __forceinline__ float apod_val(int n, float i0a) {
    float u = (float)(n - 256) * (1.0f / (float)GSZ);
    float t = 3.14159265358979f * (float)JW * u;
    float arg = ALPHA_C * ALPHA_C - t * t;
    float s = sqrtf(fabsf(arg) + 1e-20f);
    float sh;
    if (arg > 0.0f) {
        float e = __expf(s);
        sh = 0.5f * (e - 1.0f / e);
    } else {
        sh = __sinf(s);
    }
    float F = (sh / s) * ((float)JW / i0a);
    return 1.0f / F;
}

// Base-4 digit reversal of a 10-bit index (1024 = 4^5).
__device__ __forceinline__ int rev4_10(int t) {
    int x = __brev(t) >> 22;
    return ((x & 0x155) << 1) | ((x >> 1) & 0x155);
}

// ---------------------------------------------------------------------------
// Radix-4 1024-pt FFT on smem, 256 threads, input base-4-digit-reversed.
// ---------------------------------------------------------------------------
__device__ __forceinline__ void fft1024_r4(float2* s, float sign) {
    #pragma unroll
    for (int st = 0; st < 5; ++st) {
        int Q = 1 << (2 * st);
        int t = threadIdx.x;
        int g = t >> (2 * st);
        int p = t & (Q - 1);
        int base = g * (Q << 2) + p;
        float ang = sign * TWO_PI * (float)p / (float)(Q << 2);
        float s1, c1;
        __sincosf(ang, &s1, &c1);
        float c2 = c1 * c1 - s1 * s1, s2 = 2.0f * c1 * s1;
        float c3 = c1 * c2 - s1 * s2, s3 = c1 * s2 + s1 * c2;
        float2 x0 = s[base];
        float2 x1 = s[base + Q];
        float2 x2 = s[base + 2 * Q];
        float2 x3 = s[base + 3 * Q];
        float2 t1 = make_float2(x1.x * c1 - x1.y * s1, x1.x * s1 + x1.y * c1);
        float2 t2 = make_float2(x2.x * c2 - x2.y * s2, x2.x * s2 + x2.y * c2);
        float2 t3 = make_float2(x3.x * c3 - x3.y * s3, x3.x * s3 + x3.y * c3);
        float2 u0 = make_float2(x0.x + t2.x, x0.y + t2.y);
        float2 u1 = make_float2(x0.x - t2.x, x0.y - t2.y);
        float2 u2 = make_float2(t1.x + t3.x, t1.y + t3.y);
        float2 u3 = make_float2(t1.x - t3.x, t1.y - t3.y);
        float2 v  = make_float2(-u3.y, u3.x);
        s[base]         = make_float2(u0.x + u2.x, u0.y + u2.y);
        s[base + 2 * Q] = make_float2(u0.x - u2.x, u0.y - u2.y);
        s[base + Q]     = make_float2(u1.x + sign * v.x, u1.y + sign * v.y);
        s[base + 3 * Q] = make_float2(u1.x - sign * v.x, u1.y - sign * v.y);
        __syncthreads();
    }
}

// ---------------------------------------------------------------------------
// Kernel 1: apodize + pad + ifftshift + row FFT, two real rows packed/FFT.
// ---------------------------------------------------------------------------
__global__ void build_fft_rows_kernel(const float* __restrict__ img) {
    __shared__ float2 s[GSZ];
    int b = blockIdx.x;
    float i0a = i0f_dev(ALPHA_C);
    float aA = apod_val(b + 256, i0a);
    float aB = apod_val(b, i0a);
    const float* imA = img + (b + 256) * 512;
    const float* imB = img + b * 512;

    #pragma unroll
    for (int q = 0; q < 4; ++q) {
        int j = threadIdx.x + q * 256;
        float2 z = make_float2(0.0f, 0.0f);
        if (q == 0) {
            int ci = j + 256;
            float ac = apod_val(ci, i0a);
            z.x = imA[ci] * aA * ac;
            z.y = imB[ci] * aB * ac;
        } else if (q == 3) {
            int ci = j - 768;
            float ac = apod_val(ci, i0a);
            z.x = imA[ci] * aA * ac;
            z.y = imB[ci] * aB * ac;
        }
        s[rev4_10(j)] = z;
    }
    __syncthreads();
    fft1024_r4(s, -1.0f);

    float2* baseA = g_grid + (size_t)b * GSZ;
    float2* baseB = g_grid + (size_t)(b + 768) * GSZ;
    #pragma unroll
    for (int q = 0; q < 4; ++q) {
        int k = threadIdx.x + q * 256;
        float2 Zk = s[k];
        float2 Zn = s[(GSZ - k) & (GSZ - 1)];
        baseA[k] = make_float2(0.5f * (Zk.x + Zn.x), 0.5f * (Zk.y - Zn.y));
        baseB[k] = make_float2(0.5f * (Zk.y + Zn.y), 0.5f * (Zn.x - Zk.x));
    }
}

// ---------------------------------------------------------------------------
// Kernel 2: column FFT — ONLY columns j = 0..512 (Hermitian half-spectrum).
// ---------------------------------------------------------------------------
__global__ void fft_cols_kernel() {
    __shared__ float2 s[GSZ];
    int col = blockIdx.x;            // 0..512
    {
        int t0 = threadIdx.x;
        int t3 = threadIdx.x + 768;
        s[rev4_10(t0)] = g_grid[(size_t)t0 * GSZ + col];
        s[rev4_10(threadIdx.x + 256)] = make_float2(0.0f, 0.0f);
        s[rev4_10(threadIdx.x + 512)] = make_float2(0.0f, 0.0f);
        s[rev4_10(t3)] = g_grid[(size_t)t3 * GSZ + col];
    }
    __syncthreads();
    fft1024_r4(s, -1.0f);
    const float scale = 1.0f / 1024.0f;
    float2* outp = g_specT + (size_t)col * GSZ;
    #pragma unroll
    for (int q = 0; q < 4; ++q) {
        int t = threadIdx.x + q * 256;
        float2 v = s[t];
        outp[t] = make_float2(v.x * scale, v.y * scale);
    }
}

// ---------------------------------------------------------------------------
// Kernel 3 (fused): KB gather on half the detectors against the HALF spectrum
// (Hermitian mirror for j>512: row 1024-j, taps (1024-ix), conj) + 768 IFFT.
// ---------------------------------------------------------------------------
__global__ void gather_ifft_kernel(const float* __restrict__ ksp,
                                   float* __restrict__ out) {
    __shared__ float2 kd[NDET];
    __shared__ float2 sY[3][256];
    int a = blockIdx.x;

    float inv_i0a = 1.0f / i0f_dev(ALPHA_C);
    const float c = (float)GSZ / TWO_PI;

    for (int d = threadIdx.x; d < NDHALF; d += 384) {
        int po = a * NDET + d;
        float g1 = fmodf(ksp[po] * c, (float)GSZ);          if (g1 < 0.0f) g1 += (float)GSZ;
        float g2 = fmodf(ksp[KPTS + po] * c, (float)GSZ);   if (g2 < 0.0f) g2 += (float)GSZ;

        int b1 = (int)floorf(g1);
        int b2 = (int)floorf(g2);

        float wx[JW], wy[JW];
        #pragma unroll
        for (int j = 0; j < JW; ++j) {
            float u = g1 - (float)(b1 - 2 + j);
            float xx = fmaxf(fmaf(-u * u, (1.0f / 9.0f), 1.0f), 0.0f);
            wx[j] = i0_alpha_sqrt(xx) * inv_i0a;
            float v = g2 - (float)(b2 - 2 + j);
            float yy = fmaxf(fmaf(-v * v, (1.0f / 9.0f), 1.0f), 0.0f);
            wy[j] = i0_alpha_sqrt(yy) * inv_i0a;
        }

        float accx = 0.0f, accy = 0.0f;

        bool xok = (b1 >= 5 && b1 <= 1018);
        if (xok && b2 >= 2 && b2 <= 509) {
            // -------- direct fast path: rows b2-2..b2+3 all <= 512 --------
            int s0 = b1 - 2;
            int a0  = s0 & ~1;
            int off = s0 & 1;
            float w0 = off ? 0.0f  : wx[0];
            float w1 = off ? wx[0] : wx[1];
            float w2 = off ? wx[1] : wx[2];
            float w3 = off ? wx[2] : wx[3];
            float w4 = off ? wx[3] : wx[4];
            float w5 = off ? wx[4] : wx[5];
            float w6 = off ? wx[5] : 0.0f;
            const float4* base = (const float4*)(g_specT + ((size_t)(b2 - 2) * GSZ + a0));
            #pragma unroll
            for (int bb = 0; bb < JW; ++bb) {
                const float4* rp = base + (size_t)bb * (GSZ / 2);
                float4 v0 = __ldg(rp);
                float4 v1 = __ldg(rp + 1);
                float4 v2 = __ldg(rp + 2);
                float4 v3 = __ldg(rp + 3);
                float px = v0.x * w0;
                float py = v0.y * w0;
                px = fmaf(v0.z, w1, px);  py = fmaf(v0.w, w1, py);
                px = fmaf(v1.x, w2, px);  py = fmaf(v1.y, w2, py);
                px = fmaf(v1.z, w3, px);  py = fmaf(v1.w, w3, py);
                px = fmaf(v2.x, w4, px);  py = fmaf(v2.y, w4, py);
                px = fmaf(v2.z, w5, px);  py = fmaf(v2.w, w5, py);
                px = fmaf(v3.x, w6, px);  py = fmaf(v3.y, w6, py);
                accx = fmaf(px, wy[bb], accx);
                accy = fmaf(py, wy[bb], accy);
            }
        } else if (xok && b2 >= 515 && b2 <= 1020) {
            // -------- mirrored fast path: all rows j>512 --------
            // stored rows ascending: s0y..s0y+5 with wy reversed;
            // x taps ascending:      s0x..s0x+5 with wx reversed; conj -> accy -=
            int s0x = 1021 - b1;
            int s0y = 1021 - b2;
            int a0  = s0x & ~1;
            int off = s0x & 1;
            float w0 = off ? 0.0f  : wx[5];
            float w1 = off ? wx[5] : wx[4];
            float w2 = off ? wx[4] : wx[3];
            float w3 = off ? wx[3] : wx[2];
            float w4 = off ? wx[2] : wx[1];
            float w5 = off ? wx[1] : wx[0];
            float w6 = off ? wx[0] : 0.0f;
            const float4* base = (const float4*)(g_specT + ((size_t)s0y * GSZ + a0));
            #pragma unroll
            for (int bb = 0; bb < JW; ++bb) {
                const float4* rp = base + (size_t)bb * (GSZ / 2);
                float4 v0 = __ldg(rp);
                float4 v1 = __ldg(rp + 1);
                float4 v2 = __ldg(rp + 2);
                float4 v3 = __ldg(rp + 3);
                float px = v0.x * w0;
                float py = v0.y * w0;
                px = fmaf(v0.z, w1, px);  py = fmaf(v0.w, w1, py);
                px = fmaf(v1.x, w2, px);  py = fmaf(v1.y, w2, py);
                px = fmaf(v1.z, w3, px);  py = fmaf(v1.w, w3, py);
                px = fmaf(v2.x, w4, px);  py = fmaf(v2.y, w4, py);
                px = fmaf(v2.z, w5, px);  py = fmaf(v2.w, w5, py);
                px = fmaf(v3.x, w6, px);  py = fmaf(v3.y, w6, py);
                float wyb = wy[5 - bb];
                accx = fmaf(px, wyb, accx);
                accy = fmaf(-py, wyb, accy);
            }
        } else {
            // -------- generic slow path (wraps / j=512 boundary band) --------
            #pragma unroll
            for (int bb = 0; bb < JW; ++bb) {
                int iyr = (b2 - 2 + bb + GSZ) & (GSZ - 1);
                float px = 0.0f, py = 0.0f;
                if (iyr <= 512) {
                    const float2* rowp = g_specT + (size_t)iyr * GSZ;
                    #pragma unroll
                    for (int aa = 0; aa < JW; ++aa) {
                        int ixr = (b1 - 2 + aa + GSZ) & (GSZ - 1);
                        float2 v = __ldg(&rowp[ixr]);
                        px = fmaf(v.x, wx[aa], px);
                        py = fmaf(v.y, wx[aa], py);
                    }
                } else {
                    const float2* rowp = g_specT + (size_t)(GSZ - iyr) * GSZ;
                    #pragma unroll
                    for (int aa = 0; aa < JW; ++aa) {
                        int ixr = (b1 - 2 + aa + GSZ) & (GSZ - 1);
                        float2 v = __ldg(&rowp[(GSZ - ixr) & (GSZ - 1)]);
                        px = fmaf(v.x, wx[aa], px);
                        py = fmaf(-v.y, wx[aa], py);
                    }
                }
                accx = fmaf(px, wy[bb], accx);
                accy = fmaf(py, wy[bb], accy);
            }
        }

        kd[d] = make_float2(accx, accy);
        if (d > 0 && d < 384) {
            kd[NDET - d] = make_float2(accx, -accy);   // detector-dim Hermitian mirror
        }
    }
    __syncthreads();

    // ---- IFFT: 768 = 3 x 256 mixed radix; shifts folded into indices ----
    int r = threadIdx.x >> 7;
    int lt = threadIdx.x & 127;

    for (int m = lt; m < 256; m += 128) {
        int src = (3 * m + r + 384) % NDET;
        sY[r][__brev(m) >> 24] = kd[src];
    }
    __syncthreads();

    #pragma unroll
    for (int st = 0; st < 8; ++st) {
        int half = 1 << st;
        int len = half << 1;
        int grp = lt >> st;
        int pos = lt & (half - 1);
        int ii = grp * len + pos;
        int kk = ii + half;
        float ang = TWO_PI * (float)pos / (float)len;
        float sw, cw;
        __sincosf(ang, &sw, &cw);
        float2 b = sY[r][kk];
        float2 wb = make_float2(b.x * cw - b.y * sw, b.x * sw + b.y * cw);
        float2 aa = sY[r][ii];
        sY[r][ii] = make_float2(aa.x + wb.x, aa.y + wb.y);
        sY[r][kk] = make_float2(aa.x - wb.x, aa.y - wb.y);
        __syncthreads();
    }

    const float inv = 1.0f / 768.0f;
    for (int k = threadIdx.x; k < NDET; k += 384) {
        int k0 = k & 255;
        float re = sY[0][k0].x;
        float a1 = TWO_PI * (float)k * (1.0f / 768.0f);
        float s1, c1;
        __sincosf(a1, &s1, &c1);
        re += sY[1][k0].x * c1 - sY[1][k0].y * s1;
        float s2, c2;
        __sincosf(a1 + a1, &s2, &c2);
        re += sY[2][k0].x * c2 - sY[2][k0].y * s2;
        out[(size_t)a * NDET + ((k + 384) % NDET)] = re * inv;
    }
}

// ---------------------------------------------------------------------------
extern "C" void kernel_launch(void* const* d_in, const int* in_sizes, int n_in,
                              void* d_out, int out_size) {
    const float* img = (const float*)d_in[0];
    const float* ksp = (const float*)d_in[1];
    float* out = (float*)d_out;

    build_fft_rows_kernel<<<256, 256>>>(img);
    fft_cols_kernel<<<513, 256>>>();
    gather_ifft_kernel<<<NANG, 384>>>(ksp, out);
}